// round 13
// baseline (speedup 1.0000x reference)
#include <cuda_runtime.h>
#include <cuda_fp16.h>
#include <math.h>
#include <stdint.h>

// Problem constants
#define BB 2
#define TT 2048
#define EE 768
#define NH 12
#define HD 64
#define FFD 3072
#define MROWS (BB * TT)   // 4096
#define LN_EPS 1e-5f
#define NSPLIT 4

// ---------------------------------------------------------------------------
// Scratch (no allocation allowed -> __device__ globals)
// ---------------------------------------------------------------------------
__device__ __half g_qh[MROWS * EE];
__device__ __half g_kh[MROWS * EE];
__device__ __half g_vh[MROWS * EE];
__device__ __half g_attnh[MROWS * EE];
__device__ __half g_x1h[MROWS * EE];
__device__ __half g_xh[MROWS * EE];
__device__ __half g_hh[MROWS * FFD];
__device__ __half g_wqh[NH * HD * EE];
__device__ __half g_wkh[NH * HD * EE];
__device__ __half g_wvh[NH * HD * EE];
__device__ __half g_projh[EE * EE];
__device__ __half g_w1h[FFD * EE];
__device__ __half g_w2h[EE * FFD];
__device__ float g_tmp[MROWS * EE];
__device__ float g_x1[MROWS * EE];
__device__ float g_po[NSPLIT * MROWS * EE];       // split-K partial O (unnormalized)
__device__ float g_ml[NSPLIT * MROWS * NH * 2];   // split-K partial (m, l)

// ---------------------------------------------------------------------------
// Helpers
// ---------------------------------------------------------------------------
__device__ __forceinline__ void mma_f16(float* c, const unsigned* a,
                                        unsigned b0, unsigned b1) {
    asm volatile(
        "mma.sync.aligned.m16n8k16.row.col.f32.f16.f16.f32 "
        "{%0,%1,%2,%3}, {%4,%5,%6,%7}, {%8,%9}, {%0,%1,%2,%3};\n"
        : "+f"(c[0]), "+f"(c[1]), "+f"(c[2]), "+f"(c[3])
        : "r"(a[0]), "r"(a[1]), "r"(a[2]), "r"(a[3]), "r"(b0), "r"(b1));
}

__device__ __forceinline__ void ldsm4(unsigned* r, uint32_t addr) {
    asm volatile("ldmatrix.sync.aligned.m8n8.x4.shared.b16 {%0,%1,%2,%3}, [%4];"
                 : "=r"(r[0]), "=r"(r[1]), "=r"(r[2]), "=r"(r[3]) : "r"(addr));
}
__device__ __forceinline__ void ldsm4t(unsigned* r, uint32_t addr) {
    asm volatile("ldmatrix.sync.aligned.m8n8.x4.trans.shared.b16 {%0,%1,%2,%3}, [%4];"
                 : "=r"(r[0]), "=r"(r[1]), "=r"(r[2]), "=r"(r[3]) : "r"(addr));
}

__device__ __forceinline__ void cp16s(uint32_t s, const void* g) {
    asm volatile("cp.async.cg.shared.global [%0], [%1], 16;\n" :: "r"(s), "l"(g));
}
__device__ __forceinline__ void cp_commit() {
    asm volatile("cp.async.commit_group;\n");
}

__device__ __forceinline__ uint32_t smem_u32(const void* p) {
    return (uint32_t)__cvta_generic_to_shared(p);
}

// Fast exp2 (single MUFU op)
__device__ __forceinline__ float ex2(float x) {
    float r;
    asm("ex2.approx.ftz.f32 %0, %1;" : "=f"(r) : "f"(x));
    return r;
}

// ---------------------------------------------------------------------------
// Fused float -> half conversion for all 7 operand tensors (one launch).
// ---------------------------------------------------------------------------
#define CN0 (MROWS * EE / 4)      // x
#define CN1 (NH * HD * EE / 4)    // Wq / Wk / Wv
#define CN2 (EE * EE / 4)         // proj_w
#define CN3 (FFD * EE / 4)        // w1 / w2
#define CNTOT (CN0 + 3 * CN1 + CN2 + 2 * CN3)

__global__ __launch_bounds__(256)
void tohalf7_kernel(const float* __restrict__ i0, __half* __restrict__ o0,
                    const float* __restrict__ i1, __half* __restrict__ o1,
                    const float* __restrict__ i2, __half* __restrict__ o2,
                    const float* __restrict__ i3, __half* __restrict__ o3,
                    const float* __restrict__ i4, __half* __restrict__ o4,
                    const float* __restrict__ i5, __half* __restrict__ o5,
                    const float* __restrict__ i6, __half* __restrict__ o6) {
    int i = blockIdx.x * 256 + threadIdx.x;
    const float* in;
    __half* out;
    if (i < CN0) { in = i0; out = o0; }
    else if ((i -= CN0) < CN1) { in = i1; out = o1; }
    else if ((i -= CN1) < CN1) { in = i2; out = o2; }
    else if ((i -= CN1) < CN1) { in = i3; out = o3; }
    else if ((i -= CN1) < CN2) { in = i4; out = o4; }
    else if ((i -= CN2) < CN3) { in = i5; out = o5; }
    else if ((i -= CN3) < CN3) { in = i6; out = o6; }
    else return;
    float4 v = reinterpret_cast<const float4*>(in)[i];
    reinterpret_cast<__half2*>(out)[2 * i]     = __floats2half2_rn(v.x, v.y);
    reinterpret_cast<__half2*>(out)[2 * i + 1] = __floats2half2_rn(v.z, v.w);
}

// ---------------------------------------------------------------------------
// FP16 tensor-core GEMM with ldmatrix: C[M,N] = A[M,K] @ B[N,K]^T
// BM=128, BN template (128 or 64), BK=32, 256 threads, 8 warps as 4x2.
// Single-barrier 3-stage cp.async pipeline. min 3 CTAs/SM hint.
// ---------------------------------------------------------------------------
#define GROWB 80                       // bytes per smem row
#define GNS 3
#define GSMEM_OF(BN) (GNS * (128 + (BN)) * GROWB)

template <bool HAS_BIAS, bool RELU, int NZ, bool OUT_HALF, int BN>
__global__ __launch_bounds__(256, 3)
void hgemm_kernel(const __half* __restrict__ A,
                  const __half* __restrict__ B0, const __half* __restrict__ B1,
                  const __half* __restrict__ B2,
                  const float* __restrict__ bias,
                  void* __restrict__ C0v, void* __restrict__ C1v, void* __restrict__ C2v,
                  int M, int N, int K) {
    constexpr int WN     = BN / 2;
    constexpr int NGROUP = WN / 16;
    constexpr int ACCN   = WN / 8;
    constexpr int GSTGA  = 128 * GROWB;
    constexpr int GSTGB  = BN * GROWB;

    const __half* B = B0;
    void* Cv = C0v;
    if (NZ == 3) {
        if (blockIdx.z == 1) { B = B1; Cv = C1v; }
        else if (blockIdx.z == 2) { B = B2; Cv = C2v; }
    }

    extern __shared__ char smraw[];
    const uint32_t smb = smem_u32(smraw);
    const int tid  = threadIdx.x;
    const int lane = tid & 31;
    const int warp = tid >> 5;
    const int wm   = warp >> 1;
    const int wn   = warp & 1;
    const int ln4  = lane >> 2;
    const int lm4  = lane & 3;
    const int brow = blockIdx.y * 128;
    const int bcol = blockIdx.x * BN;

    const uint32_t lm_off = (uint32_t)(lane & 15) * GROWB + ((lane >> 4) << 4);
    const uint32_t a_lm = (uint32_t)(wm * 32) * GROWB + lm_off;
    const uint32_t b_lm = (uint32_t)(wn * WN) * GROWB + lm_off;

    float acc[2][ACCN][4];
#pragma unroll
    for (int mt = 0; mt < 2; mt++)
#pragma unroll
        for (int nt = 0; nt < ACCN; nt++)
#pragma unroll
            for (int i = 0; i < 4; i++) acc[mt][nt][i] = 0.0f;

    const int nk = K >> 5;

    const int lrA = tid >> 1;
    const int ljA = (tid & 1) * 2;
    const int lrB = tid >> 2;
    const int ljB = tid & 3;

    auto gload = [&](int c) {
        const int st = c % GNS;
        const uint32_t sa = smb + st * GSTGA;
        const uint32_t sb = smb + GNS * GSTGA + st * GSTGB;
        const int kb = c * 32;
        const __half* gA = A + (size_t)(brow + lrA) * K + kb + ljA * 8;
        cp16s(sa + lrA * GROWB + ljA * 16, gA);
        cp16s(sa + lrA * GROWB + (ljA + 1) * 16, gA + 8);
        if (BN == 128) {
            const __half* gB = B + (size_t)(bcol + lrA) * K + kb + ljA * 8;
            cp16s(sb + lrA * GROWB + ljA * 16, gB);
            cp16s(sb + lrA * GROWB + (ljA + 1) * 16, gB + 8);
        } else {
            const __half* gB = B + (size_t)(bcol + lrB) * K + kb + ljB * 8;
            cp16s(sb + lrB * GROWB + ljB * 16, gB);
        }
        cp_commit();
    };

#pragma unroll
    for (int c = 0; c < GNS - 1; c++) gload(c);
    asm volatile("cp.async.wait_group %0;\n" :: "n"(GNS - 2));

    for (int s = 0; s < nk; s++) {
        __syncthreads();
        const int t = s + GNS - 1;
        if (t < nk) gload(t);
        else cp_commit();

        const int st = s % GNS;
        const uint32_t sa = smb + st * GSTGA + a_lm;
        const uint32_t sb = smb + GNS * GSTGA + st * GSTGB + b_lm;
#pragma unroll
        for (int ks = 0; ks < 2; ks++) {
            unsigned af[2][4];
            ldsm4(af[0], sa + ks * 32);
            ldsm4(af[1], sa + 16 * GROWB + ks * 32);
#pragma unroll
            for (int p = 0; p < NGROUP; p++) {
                unsigned bq[4];
                ldsm4(bq, sb + p * 16 * GROWB + ks * 32);
                mma_f16(acc[0][2 * p],     af[0], bq[0], bq[2]);
                mma_f16(acc[0][2 * p + 1], af[0], bq[1], bq[3]);
                mma_f16(acc[1][2 * p],     af[1], bq[0], bq[2]);
                mma_f16(acc[1][2 * p + 1], af[1], bq[1], bq[3]);
            }
        }
        asm volatile("cp.async.wait_group %0;\n" :: "n"(GNS - 2));
    }

    // epilogue
#pragma unroll
    for (int mt = 0; mt < 2; mt++) {
        const int r = brow + wm * 32 + mt * 16 + ln4;
#pragma unroll
        for (int nt = 0; nt < ACCN; nt++) {
            const int col = bcol + wn * WN + nt * 8 + lm4 * 2;
            float2 v0 = make_float2(acc[mt][nt][0], acc[mt][nt][1]);
            float2 v1 = make_float2(acc[mt][nt][2], acc[mt][nt][3]);
            if (HAS_BIAS) {
                float bx = bias[col], by = bias[col + 1];
                v0.x += bx; v0.y += by;
                v1.x += bx; v1.y += by;
            }
            if (RELU) {
                v0.x = fmaxf(v0.x, 0.0f); v0.y = fmaxf(v0.y, 0.0f);
                v1.x = fmaxf(v1.x, 0.0f); v1.y = fmaxf(v1.y, 0.0f);
            }
            if (OUT_HALF) {
                __half* C = (__half*)Cv;
                *reinterpret_cast<__half2*>(C + (size_t)r * N + col) =
                    __floats2half2_rn(v0.x, v0.y);
                *reinterpret_cast<__half2*>(C + (size_t)(r + 8) * N + col) =
                    __floats2half2_rn(v1.x, v1.y);
            } else {
                float* C = (float*)Cv;
                *reinterpret_cast<float2*>(C + (size_t)r * N + col) = v0;
                *reinterpret_cast<float2*>(C + (size_t)(r + 8) * N + col) = v1;
            }
        }
    }
}

// ---------------------------------------------------------------------------
// 4-way split-K FP16 causal flash attention.
// Grid (T/128, B*NH, 4). Tiles ntot = 2qt+2 divided as base+(sp<rem);
// empty splits return immediately (their zero-init scratch contributes 0 to
// both combine numerator and denominator). Max serial tiles = 8.
// P in registers (c-frag == a-frag identity); log2-domain softmax; MUFU ex2.
// ---------------------------------------------------------------------------
#define ASTRW 36
#define ASTRB 144
#define AQW (128 * ASTRW)
#define AKVW (64 * ASTRW)
#define ATT_SMEM ((AQW + 4 * AKVW) * 4)   // 55296 bytes

__global__ __launch_bounds__(256)
void attn_split_kernel(const __half* __restrict__ qp, const __half* __restrict__ kp,
                       const __half* __restrict__ vp,
                       float* __restrict__ opart, float* __restrict__ mlpart) {
    extern __shared__ unsigned asm_[];
    unsigned* Qs = asm_;
    unsigned* Ks = asm_ + AQW;
    unsigned* Vs = asm_ + AQW + 2 * AKVW;

    const int qt  = (gridDim.x - 1) - blockIdx.x;   // reversed: heavy first
    const int bh  = blockIdx.y;
    const int sp  = blockIdx.z;                     // split 0..3
    const int b   = bh / NH;
    const int h   = bh % NH;

    const int ntot = 2 * qt + 2;
    const int base = ntot >> 2;
    const int rem  = ntot & 3;
    const int ntl  = base + (sp < rem ? 1 : 0);
    if (ntl == 0) return;                           // zero-init slots are inert
    const int kt0  = sp * base + (sp < rem ? sp : rem);

    const int tid = threadIdx.x;
    const int lane = tid & 31;
    const int w    = tid >> 5;
    const int ln4  = lane >> 2;
    const int lm4  = lane & 3;
    const int rb   = w * 16;

    const uint32_t smQ = smem_u32(Qs);
    const uint32_t smK = smem_u32(Ks);
    const uint32_t smV = smem_u32(Vs);

    const uint32_t lm_off = (uint32_t)(lane & 15) * ASTRB + ((lane >> 4) << 4);
    const uint32_t q_lm = smQ + (uint32_t)rb * ASTRB + lm_off;
    const uint32_t k_lm = smK + lm_off;
    const uint32_t v_lm = smV + ((uint32_t)((lane & 7) + ((lane >> 4) << 3))) * ASTRB
                              + (((lane >> 3) & 1) << 4);

    const int lrKV = tid >> 2;
    const int ljKV = tid & 3;
    auto kvload = [&](int lt) {
        const int st = lt & 1;
        const uint32_t sk = smK + st * (AKVW * 4);
        const uint32_t sv = smV + st * (AKVW * 4);
        size_t g = ((size_t)(b * TT + (kt0 + lt) * 64 + lrKV) * EE + h * HD + ljKV * 16);
        const uint32_t so = (uint32_t)lrKV * ASTRB + ljKV * 32;
        cp16s(sk + so,      kp + g);
        cp16s(sk + so + 16, kp + g + 8);
        cp16s(sv + so,      vp + g);
        cp16s(sv + so + 16, vp + g + 8);
        cp_commit();
    };

    // ---- prologue: start K/V tile 0, then load Q (plain) ----
    kvload(0);
#pragma unroll
    for (int i = 0; i < 4; i++) {
        int idx = tid + i * 256;
        int row = idx >> 3;
        int c   = idx & 7;
        uint4 vq = *reinterpret_cast<const uint4*>(
            qp + ((size_t)(b * TT + qt * 128 + row) * EE + h * HD + c * 8));
        *reinterpret_cast<uint4*>(&Qs[row * ASTRW + c * 4]) = vq;
    }
    asm volatile("cp.async.wait_group 0;\n");
    __syncthreads();

    unsigned qa[4][4];
#pragma unroll
    for (int ks = 0; ks < 4; ks++) ldsm4(qa[ks], q_lm + ks * 32);

    float o_acc[8][4];
#pragma unroll
    for (int nb = 0; nb < 8; nb++)
#pragma unroll
        for (int i = 0; i < 4; i++) o_acc[nb][i] = 0.0f;
    float m0 = -1e30f, m1 = -1e30f, l0 = 0.0f, l1 = 0.0f;
    const float scale2 = 0.125f * 1.44269504088896f;
    const int row0g = qt * 128 + rb + ln4;
    const int row1g = row0g + 8;

    for (int lt = 0; lt < ntl; lt++) {
        if (lt) __syncthreads();
        if (lt + 1 < ntl) kvload(lt + 1);
        else cp_commit();

        const uint32_t kb_ = k_lm + (lt & 1) * (AKVW * 4);
        const uint32_t vb_ = v_lm + (lt & 1) * (AKVW * 4);
        const int s0 = (kt0 + lt) * 64;

        float s[8][4];
#pragma unroll
        for (int nb = 0; nb < 8; nb++)
#pragma unroll
            for (int i = 0; i < 4; i++) s[nb][i] = 0.0f;
#pragma unroll
        for (int ks = 0; ks < 4; ks++) {
#pragma unroll
            for (int p = 0; p < 4; p++) {
                unsigned bq[4];
                ldsm4(bq, kb_ + p * 16 * ASTRB + ks * 32);
                mma_f16(s[2 * p],     qa[ks], bq[0], bq[2]);
                mma_f16(s[2 * p + 1], qa[ks], bq[1], bq[3]);
            }
        }

        if (s0 + 63 > qt * 128 + rb) {
#pragma unroll
            for (int nb = 0; nb < 8; nb++) {
                int c0 = s0 + nb * 8 + lm4 * 2;
                s[nb][0] = (c0     > row0g) ? -1e30f : s[nb][0] * scale2;
                s[nb][1] = (c0 + 1 > row0g) ? -1e30f : s[nb][1] * scale2;
                s[nb][2] = (c0     > row1g) ? -1e30f : s[nb][2] * scale2;
                s[nb][3] = (c0 + 1 > row1g) ? -1e30f : s[nb][3] * scale2;
            }
        } else {
#pragma unroll
            for (int nb = 0; nb < 8; nb++)
#pragma unroll
                for (int i = 0; i < 4; i++) s[nb][i] *= scale2;
        }

        float mx0 = -1e30f, mx1 = -1e30f;
#pragma unroll
        for (int nb = 0; nb < 8; nb++) {
            mx0 = fmaxf(mx0, fmaxf(s[nb][0], s[nb][1]));
            mx1 = fmaxf(mx1, fmaxf(s[nb][2], s[nb][3]));
        }
        mx0 = fmaxf(mx0, __shfl_xor_sync(0xffffffffu, mx0, 1));
        mx0 = fmaxf(mx0, __shfl_xor_sync(0xffffffffu, mx0, 2));
        mx1 = fmaxf(mx1, __shfl_xor_sync(0xffffffffu, mx1, 1));
        mx1 = fmaxf(mx1, __shfl_xor_sync(0xffffffffu, mx1, 2));
        float mn0 = fmaxf(m0, mx0), mn1 = fmaxf(m1, mx1);
        float alpha0 = ex2(m0 - mn0), alpha1 = ex2(m1 - mn1);
        float sum0 = 0.0f, sum1 = 0.0f;
        unsigned plo[8], phi[8];
#pragma unroll
        for (int nb = 0; nb < 8; nb++) {
            float p00 = ex2(s[nb][0] - mn0);
            float p01 = ex2(s[nb][1] - mn0);
            float p10 = ex2(s[nb][2] - mn1);
            float p11 = ex2(s[nb][3] - mn1);
            sum0 += p00 + p01;
            sum1 += p10 + p11;
            __half2 hl = __floats2half2_rn(p00, p01);
            __half2 hh2 = __floats2half2_rn(p10, p11);
            plo[nb] = *reinterpret_cast<unsigned*>(&hl);
            phi[nb] = *reinterpret_cast<unsigned*>(&hh2);
        }
        sum0 += __shfl_xor_sync(0xffffffffu, sum0, 1);
        sum0 += __shfl_xor_sync(0xffffffffu, sum0, 2);
        sum1 += __shfl_xor_sync(0xffffffffu, sum1, 1);
        sum1 += __shfl_xor_sync(0xffffffffu, sum1, 2);
        l0 = l0 * alpha0 + sum0;
        l1 = l1 * alpha1 + sum1;
        m0 = mn0; m1 = mn1;
#pragma unroll
        for (int nb = 0; nb < 8; nb++) {
            o_acc[nb][0] *= alpha0; o_acc[nb][1] *= alpha0;
            o_acc[nb][2] *= alpha1; o_acc[nb][3] *= alpha1;
        }

#pragma unroll
        for (int ks = 0; ks < 4; ks++) {
            unsigned pa[4];
            pa[0] = plo[2 * ks];
            pa[1] = phi[2 * ks];
            pa[2] = plo[2 * ks + 1];
            pa[3] = phi[2 * ks + 1];
#pragma unroll
            for (int p = 0; p < 4; p++) {
                unsigned vq[4];
                ldsm4t(vq, vb_ + ks * 16 * ASTRB + p * 32);
                mma_f16(o_acc[2 * p],     pa, vq[0], vq[2]);
                mma_f16(o_acc[2 * p + 1], pa, vq[1], vq[3]);
            }
        }
        asm volatile("cp.async.wait_group 0;\n");
    }

    // ---- write partial O (fp32, unnormalized) + (m, l) ----
    float* po = opart + (size_t)sp * MROWS * EE;
    const size_t grow0 = (size_t)(b * TT + row0g);
    const size_t grow1 = (size_t)(b * TT + row1g);
#pragma unroll
    for (int nb = 0; nb < 8; nb++) {
        int col = h * HD + nb * 8 + lm4 * 2;
        *reinterpret_cast<float2*>(po + grow0 * EE + col) =
            make_float2(o_acc[nb][0], o_acc[nb][1]);
        *reinterpret_cast<float2*>(po + grow1 * EE + col) =
            make_float2(o_acc[nb][2], o_acc[nb][3]);
    }
    if (lm4 == 0) {
        float* ml = mlpart + (size_t)sp * MROWS * NH * 2;
        ml[(grow0 * NH + h) * 2 + 0] = m0;
        ml[(grow0 * NH + h) * 2 + 1] = l0;
        ml[(grow1 * NH + h) * 2 + 0] = m1;
        ml[(grow1 * NH + h) * 2 + 1] = l1;
    }
}

// ---------------------------------------------------------------------------
// 4-way split-K combine: attnh = sum_s w_s*O_s / sum_s w_s*l_s, w_s=2^(m_s-M).
// Empty-split slots hold (m=0, l=0, O=0) -> contribute 0 to both sums.
// ---------------------------------------------------------------------------
__global__ __launch_bounds__(256)
void attn_combine_kernel(const float* __restrict__ opart,
                         const float* __restrict__ mlpart,
                         __half* __restrict__ attnh) {
    const int row = blockIdx.x;
    __half* out = attnh + (size_t)row * EE;
#pragma unroll
    for (int i = 0; i < 3; i++) {
        int c = threadIdx.x + i * 256;
        int h = c >> 6;
        float m[NSPLIT], l[NSPLIT], o[NSPLIT];
        float M = -1e30f;
#pragma unroll
        for (int s = 0; s < NSPLIT; s++) {
            const float* ml = mlpart + (size_t)s * MROWS * NH * 2 + (size_t)row * NH * 2;
            m[s] = ml[h * 2];
            l[s] = ml[h * 2 + 1];
            o[s] = opart[(size_t)s * MROWS * EE + (size_t)row * EE + c];
            M = fmaxf(M, m[s]);
        }
        float num = 0.0f, den = 0.0f;
#pragma unroll
        for (int s = 0; s < NSPLIT; s++) {
            float ws = ex2(m[s] - M);
            num += ws * o[s];
            den += ws * l[s];
        }
        out[c] = __float2half_rn(num / den);
    }
}

// ---------------------------------------------------------------------------
// Fused residual-add + LayerNorm over E=768. One block per row, 256 threads.
// ---------------------------------------------------------------------------
template <bool HALF_OUT>
__global__ __launch_bounds__(256)
void ln_kernel(const float* __restrict__ a, const float* __restrict__ res,
               const float* __restrict__ g, const float* __restrict__ bt,
               float* __restrict__ out, __half* __restrict__ outh) {
    const int row = blockIdx.x;
    const float* pa = a + (size_t)row * EE;
    const float* pr = res + (size_t)row * EE;
    float vloc[3];
    float s = 0.0f, ss = 0.0f;
#pragma unroll
    for (int i = 0; i < 3; i++) {
        int c = threadIdx.x + i * 256;
        float vv = pa[c] + pr[c];
        vloc[i] = vv;
        s += vv;
        ss += vv * vv;
    }
#pragma unroll
    for (int off = 16; off > 0; off >>= 1) {
        s  += __shfl_xor_sync(0xffffffffu, s, off);
        ss += __shfl_xor_sync(0xffffffffu, ss, off);
    }
    __shared__ float sred[16];
    __shared__ float smu, srstd;
    int w = threadIdx.x >> 5, lane = threadIdx.x & 31;
    if (lane == 0) { sred[w] = s; sred[8 + w] = ss; }
    __syncthreads();
    if (threadIdx.x == 0) {
        float S = 0.0f, SS = 0.0f;
#pragma unroll
        for (int i = 0; i < 8; i++) { S += sred[i]; SS += sred[8 + i]; }
        float mu = S * (1.0f / EE);
        float var = SS * (1.0f / EE) - mu * mu;
        smu = mu;
        srstd = rsqrtf(var + LN_EPS);
    }
    __syncthreads();
    float mu = smu, rstd = srstd;
    float* po = out + (size_t)row * EE;
    __half* ph = HALF_OUT ? (outh + (size_t)row * EE) : nullptr;
#pragma unroll
    for (int i = 0; i < 3; i++) {
        int c = threadIdx.x + i * 256;
        float vv = (vloc[i] - mu) * rstd * g[c] + bt[c];
        po[c] = vv;
        if (HALF_OUT) ph[c] = __float2half_rn(vv);
    }
}

// ---------------------------------------------------------------------------
// Launch
// ---------------------------------------------------------------------------
extern "C" void kernel_launch(void* const* d_in, const int* in_sizes, int n_in,
                              void* d_out, int out_size) {
    const float* x      = (const float*)d_in[0];
    const float* Wq     = (const float*)d_in[1];
    const float* Wk     = (const float*)d_in[2];
    const float* Wv     = (const float*)d_in[3];
    const float* proj_w = (const float*)d_in[4];
    const float* proj_b = (const float*)d_in[5];
    const float* ln1_g  = (const float*)d_in[6];
    const float* ln1_b  = (const float*)d_in[7];
    const float* w1     = (const float*)d_in[8];
    const float* b1     = (const float*)d_in[9];
    const float* w2     = (const float*)d_in[10];
    const float* b2     = (const float*)d_in[11];
    const float* ln2_g  = (const float*)d_in[12];
    const float* ln2_b  = (const float*)d_in[13];
    float* out = (float*)d_out;

    __half *qh, *kh, *vh, *attnh, *x1h, *xh, *hh;
    __half *wqh, *wkh, *wvh, *projh, *w1h, *w2h;
    float *tmp, *x1, *po, *ml;
    cudaGetSymbolAddress((void**)&qh,    g_qh);
    cudaGetSymbolAddress((void**)&kh,    g_kh);
    cudaGetSymbolAddress((void**)&vh,    g_vh);
    cudaGetSymbolAddress((void**)&attnh, g_attnh);
    cudaGetSymbolAddress((void**)&x1h,   g_x1h);
    cudaGetSymbolAddress((void**)&xh,    g_xh);
    cudaGetSymbolAddress((void**)&hh,    g_hh);
    cudaGetSymbolAddress((void**)&wqh,   g_wqh);
    cudaGetSymbolAddress((void**)&wkh,   g_wkh);
    cudaGetSymbolAddress((void**)&wvh,   g_wvh);
    cudaGetSymbolAddress((void**)&projh, g_projh);
    cudaGetSymbolAddress((void**)&w1h,   g_w1h);
    cudaGetSymbolAddress((void**)&w2h,   g_w2h);
    cudaGetSymbolAddress((void**)&tmp,   g_tmp);
    cudaGetSymbolAddress((void**)&x1,    g_x1);
    cudaGetSymbolAddress((void**)&po,    g_po);
    cudaGetSymbolAddress((void**)&ml,    g_ml);

    static bool attr_done = false;
    if (!attr_done) {
        cudaFuncSetAttribute((const void*)hgemm_kernel<false, false, 3, true, 128>,
                             cudaFuncAttributeMaxDynamicSharedMemorySize, GSMEM_OF(128));
        cudaFuncSetAttribute((const void*)hgemm_kernel<true, true, 1, true, 128>,
                             cudaFuncAttributeMaxDynamicSharedMemorySize, GSMEM_OF(128));
        cudaFuncSetAttribute((const void*)hgemm_kernel<true, false, 1, false, 64>,
                             cudaFuncAttributeMaxDynamicSharedMemorySize, GSMEM_OF(64));
        cudaFuncSetAttribute((const void*)attn_split_kernel,
                             cudaFuncAttributeMaxDynamicSharedMemorySize, ATT_SMEM);
        attr_done = true;
    }

    // ---- convert all GEMM operands to half (one launch) ----
    tohalf7_kernel<<<(CNTOT + 255) / 256, 256>>>(
        x, xh, Wq, wqh, Wk, wkh, Wv, wvh, proj_w, projh, w1, w1h, w2, w2h);

    dim3 gQKV(EE / 128, MROWS / 128, 3);    // (6, 32, 3)
    dim3 gE64(EE / 64, MROWS / 128, 1);     // (12, 32)
    dim3 gF(FFD / 128, MROWS / 128, 1);     // (24, 32)

    // Fused QKV projections
    hgemm_kernel<false, false, 3, true, 128><<<gQKV, 256, GSMEM_OF(128)>>>(
        xh, wqh, wkh, wvh, nullptr, qh, kh, vh, MROWS, EE, EE);

    // Causal attention: 4-way split-K + combine
    attn_split_kernel<<<dim3(TT / 128, BB * NH, NSPLIT), 256, ATT_SMEM>>>(
        qh, kh, vh, po, ml);
    attn_combine_kernel<<<MROWS, 256>>>(po, ml, attnh);

    // Output projection + bias (BN=64 for balance)
    hgemm_kernel<true, false, 1, false, 64><<<gE64, 256, GSMEM_OF(64)>>>(
        attnh, projh, projh, projh, proj_b, tmp, tmp, tmp, MROWS, EE, EE);
    ln_kernel<true><<<MROWS, 256>>>(tmp, x, ln1_g, ln1_b, x1, x1h);

    // FFN
    hgemm_kernel<true, true, 1, true, 128><<<gF, 256, GSMEM_OF(128)>>>(
        x1h, w1h, w1h, w1h, b1, hh, hh, hh, MROWS, FFD, EE);
    hgemm_kernel<true, false, 1, false, 64><<<gE64, 256, GSMEM_OF(64)>>>(
        hh, w2h, w2h, w2h, b2, tmp, tmp, tmp, MROWS, EE, FFD);
    ln_kernel<false><<<MROWS, 256>>>(tmp, x1, ln2_g, ln2_b, out, nullptr);
}

// round 14
// speedup vs baseline: 1.2194x; 1.2194x over previous
#include <cuda_runtime.h>
#include <cuda_fp16.h>
#include <math.h>
#include <stdint.h>

// Problem constants
#define BB 2
#define TT 2048
#define EE 768
#define NH 12
#define HD 64
#define FFD 3072
#define MROWS (BB * TT)   // 4096
#define LN_EPS 1e-5f

// ---------------------------------------------------------------------------
// Scratch (no allocation allowed -> __device__ globals)
// ---------------------------------------------------------------------------
__device__ __half g_qh[MROWS * EE];
__device__ __half g_kh[MROWS * EE];
__device__ __half g_vh[MROWS * EE];
__device__ __half g_attnh[MROWS * EE];
__device__ __half g_x1h[MROWS * EE];
__device__ __half g_xh[MROWS * EE];
__device__ __half g_hh[MROWS * FFD];
__device__ __half g_wqh[NH * HD * EE];
__device__ __half g_wkh[NH * HD * EE];
__device__ __half g_wvh[NH * HD * EE];
__device__ __half g_projh[EE * EE];
__device__ __half g_w1h[FFD * EE];
__device__ __half g_w2h[EE * FFD];
__device__ float g_tmp[MROWS * EE];
__device__ float g_x1[MROWS * EE];
__device__ float g_po[2 * MROWS * EE];          // split-K partial O (unnormalized)
__device__ float g_ml[2 * MROWS * NH * 2];      // split-K partial (m, l)

// ---------------------------------------------------------------------------
// Helpers
// ---------------------------------------------------------------------------
__device__ __forceinline__ void mma_f16(float* c, const unsigned* a,
                                        unsigned b0, unsigned b1) {
    asm volatile(
        "mma.sync.aligned.m16n8k16.row.col.f32.f16.f16.f32 "
        "{%0,%1,%2,%3}, {%4,%5,%6,%7}, {%8,%9}, {%0,%1,%2,%3};\n"
        : "+f"(c[0]), "+f"(c[1]), "+f"(c[2]), "+f"(c[3])
        : "r"(a[0]), "r"(a[1]), "r"(a[2]), "r"(a[3]), "r"(b0), "r"(b1));
}

__device__ __forceinline__ void ldsm4(unsigned* r, uint32_t addr) {
    asm volatile("ldmatrix.sync.aligned.m8n8.x4.shared.b16 {%0,%1,%2,%3}, [%4];"
                 : "=r"(r[0]), "=r"(r[1]), "=r"(r[2]), "=r"(r[3]) : "r"(addr));
}
__device__ __forceinline__ void ldsm4t(unsigned* r, uint32_t addr) {
    asm volatile("ldmatrix.sync.aligned.m8n8.x4.trans.shared.b16 {%0,%1,%2,%3}, [%4];"
                 : "=r"(r[0]), "=r"(r[1]), "=r"(r[2]), "=r"(r[3]) : "r"(addr));
}

__device__ __forceinline__ void cp16s(uint32_t s, const void* g) {
    asm volatile("cp.async.cg.shared.global [%0], [%1], 16;\n" :: "r"(s), "l"(g));
}
__device__ __forceinline__ void cp_commit() {
    asm volatile("cp.async.commit_group;\n");
}

__device__ __forceinline__ uint32_t smem_u32(const void* p) {
    return (uint32_t)__cvta_generic_to_shared(p);
}

// Fast exp2 (single MUFU op; avoids the slow accurate exp2f software path)
__device__ __forceinline__ float ex2(float x) {
    float r;
    asm("ex2.approx.ftz.f32 %0, %1;" : "=f"(r) : "f"(x));
    return r;
}

// ---------------------------------------------------------------------------
// Fused float -> half conversion for all 7 operand tensors (one launch).
// ---------------------------------------------------------------------------
#define CN0 (MROWS * EE / 4)      // x
#define CN1 (NH * HD * EE / 4)    // Wq / Wk / Wv
#define CN2 (EE * EE / 4)         // proj_w
#define CN3 (FFD * EE / 4)        // w1 / w2
#define CNTOT (CN0 + 3 * CN1 + CN2 + 2 * CN3)

__global__ __launch_bounds__(256)
void tohalf7_kernel(const float* __restrict__ i0, __half* __restrict__ o0,
                    const float* __restrict__ i1, __half* __restrict__ o1,
                    const float* __restrict__ i2, __half* __restrict__ o2,
                    const float* __restrict__ i3, __half* __restrict__ o3,
                    const float* __restrict__ i4, __half* __restrict__ o4,
                    const float* __restrict__ i5, __half* __restrict__ o5,
                    const float* __restrict__ i6, __half* __restrict__ o6) {
    int i = blockIdx.x * 256 + threadIdx.x;
    const float* in;
    __half* out;
    if (i < CN0) { in = i0; out = o0; }
    else if ((i -= CN0) < CN1) { in = i1; out = o1; }
    else if ((i -= CN1) < CN1) { in = i2; out = o2; }
    else if ((i -= CN1) < CN1) { in = i3; out = o3; }
    else if ((i -= CN1) < CN2) { in = i4; out = o4; }
    else if ((i -= CN2) < CN3) { in = i5; out = o5; }
    else if ((i -= CN3) < CN3) { in = i6; out = o6; }
    else return;
    float4 v = reinterpret_cast<const float4*>(in)[i];
    reinterpret_cast<__half2*>(out)[2 * i]     = __floats2half2_rn(v.x, v.y);
    reinterpret_cast<__half2*>(out)[2 * i + 1] = __floats2half2_rn(v.z, v.w);
}

// ---------------------------------------------------------------------------
// FP16 tensor-core GEMM with ldmatrix: C[M,N] = A[M,K] @ B[N,K]^T
// BM=128, BN template (128 or 64), BK=32, 256 threads, 8 warps as 4x2.
// Single-barrier 3-stage cp.async pipeline. (No minctas hint — R13 showed it
// regresses.)
// ---------------------------------------------------------------------------
#define GROWB 80                       // bytes per smem row
#define GNS 3
#define GSMEM_OF(BN) (GNS * (128 + (BN)) * GROWB)

template <bool HAS_BIAS, bool RELU, int NZ, bool OUT_HALF, int BN>
__global__ __launch_bounds__(256)
void hgemm_kernel(const __half* __restrict__ A,
                  const __half* __restrict__ B0, const __half* __restrict__ B1,
                  const __half* __restrict__ B2,
                  const float* __restrict__ bias,
                  void* __restrict__ C0v, void* __restrict__ C1v, void* __restrict__ C2v,
                  int M, int N, int K) {
    constexpr int WN     = BN / 2;
    constexpr int NGROUP = WN / 16;
    constexpr int ACCN   = WN / 8;
    constexpr int GSTGA  = 128 * GROWB;
    constexpr int GSTGB  = BN * GROWB;

    const __half* B = B0;
    void* Cv = C0v;
    if (NZ == 3) {
        if (blockIdx.z == 1) { B = B1; Cv = C1v; }
        else if (blockIdx.z == 2) { B = B2; Cv = C2v; }
    }

    extern __shared__ char smraw[];
    const uint32_t smb = smem_u32(smraw);
    const int tid  = threadIdx.x;
    const int lane = tid & 31;
    const int warp = tid >> 5;
    const int wm   = warp >> 1;
    const int wn   = warp & 1;
    const int ln4  = lane >> 2;
    const int lm4  = lane & 3;
    const int brow = blockIdx.y * 128;
    const int bcol = blockIdx.x * BN;

    const uint32_t lm_off = (uint32_t)(lane & 15) * GROWB + ((lane >> 4) << 4);
    const uint32_t a_lm = (uint32_t)(wm * 32) * GROWB + lm_off;
    const uint32_t b_lm = (uint32_t)(wn * WN) * GROWB + lm_off;

    float acc[2][ACCN][4];
#pragma unroll
    for (int mt = 0; mt < 2; mt++)
#pragma unroll
        for (int nt = 0; nt < ACCN; nt++)
#pragma unroll
            for (int i = 0; i < 4; i++) acc[mt][nt][i] = 0.0f;

    const int nk = K >> 5;

    const int lrA = tid >> 1;
    const int ljA = (tid & 1) * 2;
    const int lrB = tid >> 2;
    const int ljB = tid & 3;

    auto gload = [&](int c) {
        const int st = c % GNS;
        const uint32_t sa = smb + st * GSTGA;
        const uint32_t sb = smb + GNS * GSTGA + st * GSTGB;
        const int kb = c * 32;
        const __half* gA = A + (size_t)(brow + lrA) * K + kb + ljA * 8;
        cp16s(sa + lrA * GROWB + ljA * 16, gA);
        cp16s(sa + lrA * GROWB + (ljA + 1) * 16, gA + 8);
        if (BN == 128) {
            const __half* gB = B + (size_t)(bcol + lrA) * K + kb + ljA * 8;
            cp16s(sb + lrA * GROWB + ljA * 16, gB);
            cp16s(sb + lrA * GROWB + (ljA + 1) * 16, gB + 8);
        } else {
            const __half* gB = B + (size_t)(bcol + lrB) * K + kb + ljB * 8;
            cp16s(sb + lrB * GROWB + ljB * 16, gB);
        }
        cp_commit();
    };

#pragma unroll
    for (int c = 0; c < GNS - 1; c++) gload(c);
    asm volatile("cp.async.wait_group %0;\n" :: "n"(GNS - 2));

    for (int s = 0; s < nk; s++) {
        __syncthreads();
        const int t = s + GNS - 1;
        if (t < nk) gload(t);
        else cp_commit();

        const int st = s % GNS;
        const uint32_t sa = smb + st * GSTGA + a_lm;
        const uint32_t sb = smb + GNS * GSTGA + st * GSTGB + b_lm;
#pragma unroll
        for (int ks = 0; ks < 2; ks++) {
            unsigned af[2][4];
            ldsm4(af[0], sa + ks * 32);
            ldsm4(af[1], sa + 16 * GROWB + ks * 32);
#pragma unroll
            for (int p = 0; p < NGROUP; p++) {
                unsigned bq[4];
                ldsm4(bq, sb + p * 16 * GROWB + ks * 32);
                mma_f16(acc[0][2 * p],     af[0], bq[0], bq[2]);
                mma_f16(acc[0][2 * p + 1], af[0], bq[1], bq[3]);
                mma_f16(acc[1][2 * p],     af[1], bq[0], bq[2]);
                mma_f16(acc[1][2 * p + 1], af[1], bq[1], bq[3]);
            }
        }
        asm volatile("cp.async.wait_group %0;\n" :: "n"(GNS - 2));
    }

    // epilogue
#pragma unroll
    for (int mt = 0; mt < 2; mt++) {
        const int r = brow + wm * 32 + mt * 16 + ln4;
#pragma unroll
        for (int nt = 0; nt < ACCN; nt++) {
            const int col = bcol + wn * WN + nt * 8 + lm4 * 2;
            float2 v0 = make_float2(acc[mt][nt][0], acc[mt][nt][1]);
            float2 v1 = make_float2(acc[mt][nt][2], acc[mt][nt][3]);
            if (HAS_BIAS) {
                float bx = bias[col], by = bias[col + 1];
                v0.x += bx; v0.y += by;
                v1.x += bx; v1.y += by;
            }
            if (RELU) {
                v0.x = fmaxf(v0.x, 0.0f); v0.y = fmaxf(v0.y, 0.0f);
                v1.x = fmaxf(v1.x, 0.0f); v1.y = fmaxf(v1.y, 0.0f);
            }
            if (OUT_HALF) {
                __half* C = (__half*)Cv;
                *reinterpret_cast<__half2*>(C + (size_t)r * N + col) =
                    __floats2half2_rn(v0.x, v0.y);
                *reinterpret_cast<__half2*>(C + (size_t)(r + 8) * N + col) =
                    __floats2half2_rn(v1.x, v1.y);
            } else {
                float* C = (float*)Cv;
                *reinterpret_cast<float2*>(C + (size_t)r * N + col) = v0;
                *reinterpret_cast<float2*>(C + (size_t)(r + 8) * N + col) = v1;
            }
        }
    }
}

// ---------------------------------------------------------------------------
// 2-way split-K FP16 causal flash attention (verified R12 configuration).
// Grid (T/128, B*NH, 2): split sp covers key tiles [sp*(qt+1), (sp+1)*(qt+1)).
// Each split writes UNNORMALIZED O (fp32) + (m, l); combine merges.
// P in registers (c-frag == a-frag identity); log2-domain softmax; MUFU ex2.
// ---------------------------------------------------------------------------
#define ASTRW 36
#define ASTRB 144
#define AQW (128 * ASTRW)
#define AKVW (64 * ASTRW)
#define ATT_SMEM ((AQW + 4 * AKVW) * 4)   // 55296 bytes

__global__ __launch_bounds__(256)
void attn_split_kernel(const __half* __restrict__ qp, const __half* __restrict__ kp,
                       const __half* __restrict__ vp,
                       float* __restrict__ opart, float* __restrict__ mlpart) {
    extern __shared__ unsigned asm_[];
    unsigned* Qs = asm_;                     // Q staging (prologue only)
    unsigned* Ks = asm_ + AQW;               // 2 stages
    unsigned* Vs = asm_ + AQW + 2 * AKVW;    // 2 stages

    const int qt  = (gridDim.x - 1) - blockIdx.x;   // reversed: heavy first
    const int bh  = blockIdx.y;
    const int sp  = blockIdx.z;              // split 0 / 1
    const int b   = bh / NH;
    const int h   = bh % NH;
    const int tid = threadIdx.x;
    const int lane = tid & 31;
    const int w    = tid >> 5;       // 0..7
    const int ln4  = lane >> 2;      // 0..7
    const int lm4  = lane & 3;       // 0..3
    const int rb   = w * 16;         // warp's query-row base (0..112)

    const int ntl = qt + 1;          // tiles in this split
    const int kt0 = sp * ntl;        // first global key tile

    const uint32_t smQ = smem_u32(Qs);
    const uint32_t smK = smem_u32(Ks);
    const uint32_t smV = smem_u32(Vs);

    const uint32_t lm_off = (uint32_t)(lane & 15) * ASTRB + ((lane >> 4) << 4);
    const uint32_t q_lm = smQ + (uint32_t)rb * ASTRB + lm_off;
    const uint32_t k_lm = smK + lm_off;
    const uint32_t v_lm = smV + ((uint32_t)((lane & 7) + ((lane >> 4) << 3))) * ASTRB
                              + (((lane >> 3) & 1) << 4);

    // K/V tile loader (local tile index lt; global tile = kt0 + lt)
    const int lrKV = tid >> 2;           // 0..63
    const int ljKV = tid & 3;            // 0..3
    auto kvload = [&](int lt) {
        const int st = lt & 1;
        const uint32_t sk = smK + st * (AKVW * 4);
        const uint32_t sv = smV + st * (AKVW * 4);
        size_t g = ((size_t)(b * TT + (kt0 + lt) * 64 + lrKV) * EE + h * HD + ljKV * 16);
        const uint32_t so = (uint32_t)lrKV * ASTRB + ljKV * 32;
        cp16s(sk + so,      kp + g);
        cp16s(sk + so + 16, kp + g + 8);
        cp16s(sv + so,      vp + g);
        cp16s(sv + so + 16, vp + g + 8);
        cp_commit();
    };

    // ---- prologue: start K/V tile 0, then load Q (plain) ----
    kvload(0);
#pragma unroll
    for (int i = 0; i < 4; i++) {
        int idx = tid + i * 256;
        int row = idx >> 3;               // 0..127
        int c   = idx & 7;
        uint4 vq = *reinterpret_cast<const uint4*>(
            qp + ((size_t)(b * TT + qt * 128 + row) * EE + h * HD + c * 8));
        *reinterpret_cast<uint4*>(&Qs[row * ASTRW + c * 4]) = vq;
    }
    asm volatile("cp.async.wait_group 0;\n");
    __syncthreads();

    // ---- Q a-fragments (4 k16 chunks x 4 regs), held in registers ----
    unsigned qa[4][4];
#pragma unroll
    for (int ks = 0; ks < 4; ks++) ldsm4(qa[ks], q_lm + ks * 32);

    float o_acc[8][4];
#pragma unroll
    for (int nb = 0; nb < 8; nb++)
#pragma unroll
        for (int i = 0; i < 4; i++) o_acc[nb][i] = 0.0f;
    float m0 = -1e30f, m1 = -1e30f, l0 = 0.0f, l1 = 0.0f;
    const float scale2 = 0.125f * 1.44269504088896f;   // 1/sqrt(64) * log2(e)
    const int row0g = qt * 128 + rb + ln4;
    const int row1g = row0g + 8;

    for (int lt = 0; lt < ntl; lt++) {
        if (lt) __syncthreads();
        if (lt + 1 < ntl) kvload(lt + 1);
        else cp_commit();

        const uint32_t kb_ = k_lm + (lt & 1) * (AKVW * 4);
        const uint32_t vb_ = v_lm + (lt & 1) * (AKVW * 4);
        const int s0 = (kt0 + lt) * 64;

        // ---- S = Q K^T : warp computes 16x64 ----
        float s[8][4];
#pragma unroll
        for (int nb = 0; nb < 8; nb++)
#pragma unroll
            for (int i = 0; i < 4; i++) s[nb][i] = 0.0f;
#pragma unroll
        for (int ks = 0; ks < 4; ks++) {
#pragma unroll
            for (int p = 0; p < 4; p++) {
                unsigned bq[4];
                ldsm4(bq, kb_ + p * 16 * ASTRB + ks * 32);
                mma_f16(s[2 * p],     qa[ks], bq[0], bq[2]);
                mma_f16(s[2 * p + 1], qa[ks], bq[1], bq[3]);
            }
        }

        // ---- scale (log2 domain) + causal mask ----
        if (s0 + 63 > qt * 128 + rb) {
#pragma unroll
            for (int nb = 0; nb < 8; nb++) {
                int c0 = s0 + nb * 8 + lm4 * 2;
                s[nb][0] = (c0     > row0g) ? -1e30f : s[nb][0] * scale2;
                s[nb][1] = (c0 + 1 > row0g) ? -1e30f : s[nb][1] * scale2;
                s[nb][2] = (c0     > row1g) ? -1e30f : s[nb][2] * scale2;
                s[nb][3] = (c0 + 1 > row1g) ? -1e30f : s[nb][3] * scale2;
            }
        } else {
#pragma unroll
            for (int nb = 0; nb < 8; nb++)
#pragma unroll
                for (int i = 0; i < 4; i++) s[nb][i] *= scale2;
        }

        // ---- online softmax (fp32, base 2); P packed into registers ----
        float mx0 = -1e30f, mx1 = -1e30f;
#pragma unroll
        for (int nb = 0; nb < 8; nb++) {
            mx0 = fmaxf(mx0, fmaxf(s[nb][0], s[nb][1]));
            mx1 = fmaxf(mx1, fmaxf(s[nb][2], s[nb][3]));
        }
        mx0 = fmaxf(mx0, __shfl_xor_sync(0xffffffffu, mx0, 1));
        mx0 = fmaxf(mx0, __shfl_xor_sync(0xffffffffu, mx0, 2));
        mx1 = fmaxf(mx1, __shfl_xor_sync(0xffffffffu, mx1, 1));
        mx1 = fmaxf(mx1, __shfl_xor_sync(0xffffffffu, mx1, 2));
        float mn0 = fmaxf(m0, mx0), mn1 = fmaxf(m1, mx1);
        float alpha0 = ex2(m0 - mn0), alpha1 = ex2(m1 - mn1);
        float sum0 = 0.0f, sum1 = 0.0f;
        unsigned plo[8], phi[8];          // P a-fragment halves (row, row+8)
#pragma unroll
        for (int nb = 0; nb < 8; nb++) {
            float p00 = ex2(s[nb][0] - mn0);
            float p01 = ex2(s[nb][1] - mn0);
            float p10 = ex2(s[nb][2] - mn1);
            float p11 = ex2(s[nb][3] - mn1);
            sum0 += p00 + p01;
            sum1 += p10 + p11;
            __half2 hl = __floats2half2_rn(p00, p01);
            __half2 hh2 = __floats2half2_rn(p10, p11);
            plo[nb] = *reinterpret_cast<unsigned*>(&hl);
            phi[nb] = *reinterpret_cast<unsigned*>(&hh2);
        }
        sum0 += __shfl_xor_sync(0xffffffffu, sum0, 1);
        sum0 += __shfl_xor_sync(0xffffffffu, sum0, 2);
        sum1 += __shfl_xor_sync(0xffffffffu, sum1, 1);
        sum1 += __shfl_xor_sync(0xffffffffu, sum1, 2);
        l0 = l0 * alpha0 + sum0;
        l1 = l1 * alpha1 + sum1;
        m0 = mn0; m1 = mn1;
#pragma unroll
        for (int nb = 0; nb < 8; nb++) {
            o_acc[nb][0] *= alpha0; o_acc[nb][1] *= alpha0;
            o_acc[nb][2] *= alpha1; o_acc[nb][3] *= alpha1;
        }

        // ---- O += P V : P a-frags from registers, V b-frags via ldsm.trans ----
#pragma unroll
        for (int ks = 0; ks < 4; ks++) {
            unsigned pa[4];
            pa[0] = plo[2 * ks];
            pa[1] = phi[2 * ks];
            pa[2] = plo[2 * ks + 1];
            pa[3] = phi[2 * ks + 1];
#pragma unroll
            for (int p = 0; p < 4; p++) {
                unsigned vq[4];
                ldsm4t(vq, vb_ + ks * 16 * ASTRB + p * 32);
                mma_f16(o_acc[2 * p],     pa, vq[0], vq[2]);
                mma_f16(o_acc[2 * p + 1], pa, vq[1], vq[3]);
            }
        }
        asm volatile("cp.async.wait_group 0;\n");
    }

    // ---- write partial O (fp32, unnormalized) + (m, l) ----
    float* po = opart + (size_t)sp * MROWS * EE;
    const size_t grow0 = (size_t)(b * TT + row0g);
    const size_t grow1 = (size_t)(b * TT + row1g);
#pragma unroll
    for (int nb = 0; nb < 8; nb++) {
        int col = h * HD + nb * 8 + lm4 * 2;
        *reinterpret_cast<float2*>(po + grow0 * EE + col) =
            make_float2(o_acc[nb][0], o_acc[nb][1]);
        *reinterpret_cast<float2*>(po + grow1 * EE + col) =
            make_float2(o_acc[nb][2], o_acc[nb][3]);
    }
    if (lm4 == 0) {
        float* ml = mlpart + (size_t)sp * MROWS * NH * 2;
        ml[(grow0 * NH + h) * 2 + 0] = m0;
        ml[(grow0 * NH + h) * 2 + 1] = l0;
        ml[(grow1 * NH + h) * 2 + 0] = m1;
        ml[(grow1 * NH + h) * 2 + 1] = l1;
    }
}

// ---------------------------------------------------------------------------
// Split-K combine: attnh = (w0*O0 + w1*O1) / (w0*l0 + w1*l1), w = 2^(m - M).
// 2 rows per block (grid MROWS/2, 256 threads, 6 elems/thread) for ILP.
// ---------------------------------------------------------------------------
__global__ __launch_bounds__(256)
void attn_combine_kernel(const float* __restrict__ opart,
                         const float* __restrict__ mlpart,
                         __half* __restrict__ attnh) {
#pragma unroll
    for (int r = 0; r < 2; r++) {
        const int row = blockIdx.x * 2 + r;
        const float* O0 = opart + (size_t)row * EE;
        const float* O1 = opart + (size_t)MROWS * EE + (size_t)row * EE;
        const float* ml0 = mlpart + (size_t)row * NH * 2;
        const float* ml1 = mlpart + (size_t)MROWS * NH * 2 + (size_t)row * NH * 2;
        __half* out = attnh + (size_t)row * EE;
#pragma unroll
        for (int i = 0; i < 3; i++) {
            int c = threadIdx.x + i * 256;
            int h = c >> 6;
            float m0 = ml0[h * 2], l0 = ml0[h * 2 + 1];
            float m1 = ml1[h * 2], l1 = ml1[h * 2 + 1];
            float M = fmaxf(m0, m1);
            float w0 = ex2(m0 - M), w1 = ex2(m1 - M);
            float d = w0 * l0 + w1 * l1;
            float v = (w0 * O0[c] + w1 * O1[c]) / d;
            out[c] = __float2half_rn(v);
        }
    }
}

// ---------------------------------------------------------------------------
// Fused residual-add + LayerNorm over E=768. One block per row, 256 threads.
// ---------------------------------------------------------------------------
template <bool HALF_OUT>
__global__ __launch_bounds__(256)
void ln_kernel(const float* __restrict__ a, const float* __restrict__ res,
               const float* __restrict__ g, const float* __restrict__ bt,
               float* __restrict__ out, __half* __restrict__ outh) {
    const int row = blockIdx.x;
    const float* pa = a + (size_t)row * EE;
    const float* pr = res + (size_t)row * EE;
    float vloc[3];
    float s = 0.0f, ss = 0.0f;
#pragma unroll
    for (int i = 0; i < 3; i++) {
        int c = threadIdx.x + i * 256;
        float vv = pa[c] + pr[c];
        vloc[i] = vv;
        s += vv;
        ss += vv * vv;
    }
#pragma unroll
    for (int off = 16; off > 0; off >>= 1) {
        s  += __shfl_xor_sync(0xffffffffu, s, off);
        ss += __shfl_xor_sync(0xffffffffu, ss, off);
    }
    __shared__ float sred[16];
    __shared__ float smu, srstd;
    int w = threadIdx.x >> 5, lane = threadIdx.x & 31;
    if (lane == 0) { sred[w] = s; sred[8 + w] = ss; }
    __syncthreads();
    if (threadIdx.x == 0) {
        float S = 0.0f, SS = 0.0f;
#pragma unroll
        for (int i = 0; i < 8; i++) { S += sred[i]; SS += sred[8 + i]; }
        float mu = S * (1.0f / EE);
        float var = SS * (1.0f / EE) - mu * mu;
        smu = mu;
        srstd = rsqrtf(var + LN_EPS);
    }
    __syncthreads();
    float mu = smu, rstd = srstd;
    float* po = out + (size_t)row * EE;
    __half* ph = HALF_OUT ? (outh + (size_t)row * EE) : nullptr;
#pragma unroll
    for (int i = 0; i < 3; i++) {
        int c = threadIdx.x + i * 256;
        float vv = (vloc[i] - mu) * rstd * g[c] + bt[c];
        po[c] = vv;
        if (HALF_OUT) ph[c] = __float2half_rn(vv);
    }
}

// ---------------------------------------------------------------------------
// Launch
// ---------------------------------------------------------------------------
extern "C" void kernel_launch(void* const* d_in, const int* in_sizes, int n_in,
                              void* d_out, int out_size) {
    const float* x      = (const float*)d_in[0];
    const float* Wq     = (const float*)d_in[1];
    const float* Wk     = (const float*)d_in[2];
    const float* Wv     = (const float*)d_in[3];
    const float* proj_w = (const float*)d_in[4];
    const float* proj_b = (const float*)d_in[5];
    const float* ln1_g  = (const float*)d_in[6];
    const float* ln1_b  = (const float*)d_in[7];
    const float* w1     = (const float*)d_in[8];
    const float* b1     = (const float*)d_in[9];
    const float* w2     = (const float*)d_in[10];
    const float* b2     = (const float*)d_in[11];
    const float* ln2_g  = (const float*)d_in[12];
    const float* ln2_b  = (const float*)d_in[13];
    float* out = (float*)d_out;

    __half *qh, *kh, *vh, *attnh, *x1h, *xh, *hh;
    __half *wqh, *wkh, *wvh, *projh, *w1h, *w2h;
    float *tmp, *x1, *po, *ml;
    cudaGetSymbolAddress((void**)&qh,    g_qh);
    cudaGetSymbolAddress((void**)&kh,    g_kh);
    cudaGetSymbolAddress((void**)&vh,    g_vh);
    cudaGetSymbolAddress((void**)&attnh, g_attnh);
    cudaGetSymbolAddress((void**)&x1h,   g_x1h);
    cudaGetSymbolAddress((void**)&xh,    g_xh);
    cudaGetSymbolAddress((void**)&hh,    g_hh);
    cudaGetSymbolAddress((void**)&wqh,   g_wqh);
    cudaGetSymbolAddress((void**)&wkh,   g_wkh);
    cudaGetSymbolAddress((void**)&wvh,   g_wvh);
    cudaGetSymbolAddress((void**)&projh, g_projh);
    cudaGetSymbolAddress((void**)&w1h,   g_w1h);
    cudaGetSymbolAddress((void**)&w2h,   g_w2h);
    cudaGetSymbolAddress((void**)&tmp,   g_tmp);
    cudaGetSymbolAddress((void**)&x1,    g_x1);
    cudaGetSymbolAddress((void**)&po,    g_po);
    cudaGetSymbolAddress((void**)&ml,    g_ml);

    static bool attr_done = false;
    if (!attr_done) {
        cudaFuncSetAttribute((const void*)hgemm_kernel<false, false, 3, true, 128>,
                             cudaFuncAttributeMaxDynamicSharedMemorySize, GSMEM_OF(128));
        cudaFuncSetAttribute((const void*)hgemm_kernel<true, true, 1, true, 128>,
                             cudaFuncAttributeMaxDynamicSharedMemorySize, GSMEM_OF(128));
        cudaFuncSetAttribute((const void*)hgemm_kernel<true, false, 1, false, 64>,
                             cudaFuncAttributeMaxDynamicSharedMemorySize, GSMEM_OF(64));
        cudaFuncSetAttribute((const void*)attn_split_kernel,
                             cudaFuncAttributeMaxDynamicSharedMemorySize, ATT_SMEM);
        attr_done = true;
    }

    // ---- convert all GEMM operands to half (one launch) ----
    tohalf7_kernel<<<(CNTOT + 255) / 256, 256>>>(
        x, xh, Wq, wqh, Wk, wkh, Wv, wvh, proj_w, projh, w1, w1h, w2, w2h);

    dim3 gQKV(EE / 128, MROWS / 128, 3);    // (6, 32, 3)
    dim3 gE64(EE / 64, MROWS / 128, 1);     // (12, 32)
    dim3 gF(FFD / 128, MROWS / 128, 1);     // (24, 32)

    // Fused QKV projections
    hgemm_kernel<false, false, 3, true, 128><<<gQKV, 256, GSMEM_OF(128)>>>(
        xh, wqh, wkh, wvh, nullptr, qh, kh, vh, MROWS, EE, EE);

    // Causal attention: 2-way split-K + combine
    attn_split_kernel<<<dim3(TT / 128, BB * NH, 2), 256, ATT_SMEM>>>(
        qh, kh, vh, po, ml);
    attn_combine_kernel<<<MROWS / 2, 256>>>(po, ml, attnh);

    // Output projection + bias (BN=64 for balance)
    hgemm_kernel<true, false, 1, false, 64><<<gE64, 256, GSMEM_OF(64)>>>(
        attnh, projh, projh, projh, proj_b, tmp, tmp, tmp, MROWS, EE, EE);
    ln_kernel<true><<<MROWS, 256>>>(tmp, x, ln1_g, ln1_b, x1, x1h);

    // FFN
    hgemm_kernel<true, true, 1, true, 128><<<gF, 256, GSMEM_OF(128)>>>(
        x1h, w1h, w1h, w1h, b1, hh, hh, hh, MROWS, FFD, EE);
    hgemm_kernel<true, false, 1, false, 64><<<gE64, 256, GSMEM_OF(64)>>>(
        hh, w2h, w2h, w2h, b2, tmp, tmp, tmp, MROWS, EE, FFD);
    ln_kernel<false><<<MROWS, 256>>>(tmp, x1, ln2_g, ln2_b, out, nullptr);
}